// round 1
// baseline (speedup 1.0000x reference)
#include <cuda_runtime.h>
#include <math.h>

#define D_NUM 4000
#define T_NUM 2000
#define FEAT  256
#define UNITS 200
#define TOPK  10
#define NCHUNK 16

// ---------------- scratch (device globals; no runtime allocation) ----------------
__device__ float g_S[(size_t)D_NUM * T_NUM];        // learned relation graph / R_res
__device__ float g_catd[(size_t)D_NUM * 3 * FEAT];  // concat buffer drugs
__device__ float g_catt[(size_t)T_NUM * 3 * FEAT];  // concat buffer targets
__device__ float g_hd[(size_t)D_NUM * FEAT];        // current H_d
__device__ float g_ht[(size_t)T_NUM * FEAT];        // current H_t
__device__ float g_hdp[(size_t)D_NUM * UNITS];      // projected Hd
__device__ float g_htp[(size_t)T_NUM * UNITS];      // projected Ht
__device__ float g_sd[D_NUM];                       // rsqrt(safe(rowsum(D)))
__device__ float g_st[T_NUM];                       // rsqrt(safe(rowsum(T)))
__device__ float g_nd[D_NUM];                       // bipartite row norms
__device__ float g_nt[T_NUM];                       // bipartite col norms
__device__ float g_part[NCHUNK * T_NUM];            // colsum partials

// ---------------- reductions ----------------
__global__ void rowsum_rsqrt(const float* __restrict__ A, int rows, int cols,
                             float* __restrict__ out) {
    int row = blockIdx.x;
    if (row >= rows) return;
    const float* a = A + (size_t)row * cols;
    float s = 0.f;
    for (int j = threadIdx.x; j < cols; j += blockDim.x) s += a[j];
    __shared__ float red[256];
    red[threadIdx.x] = s;
    __syncthreads();
    for (int off = 128; off > 0; off >>= 1) {
        if (threadIdx.x < off) red[threadIdx.x] += red[threadIdx.x + off];
        __syncthreads();
    }
    if (threadIdx.x == 0) {
        float n = red[0];
        if (n == 0.f) n = 1.f;
        out[row] = rsqrtf(n);
    }
}

__global__ void colsum_partial(const float* __restrict__ A, int rows, int cols,
                               float* __restrict__ part) {
    int j = blockIdx.x * blockDim.x + threadIdx.x;
    if (j >= cols) return;
    int chunk = (rows + NCHUNK - 1) / NCHUNK;
    int r0 = blockIdx.y * chunk;
    int r1 = r0 + chunk; if (r1 > rows) r1 = rows;
    float s = 0.f;
    for (int i = r0; i < r1; i++) s += A[(size_t)i * cols + j];
    part[blockIdx.y * cols + j] = s;
}

__global__ void colsum_finish(const float* __restrict__ part, int cols,
                              float* __restrict__ out) {
    int j = blockIdx.x * blockDim.x + threadIdx.x;
    if (j >= cols) return;
    float s = 0.f;
    for (int c = 0; c < NCHUNK; c++) s += part[c * cols + j];
    if (s == 0.f) s = 1.f;
    out[j] = rsqrtf(s);
}

// ---------------- top-k prune (exact stable-sort tie semantics: min index wins) ---
__global__ void topk_kernel(float* __restrict__ S, float* __restrict__ nd_out) {
    __shared__ float sv[T_NUM];
    __shared__ float rv[256];
    __shared__ int   ri[256];
    __shared__ int   sel[TOPK];
    __shared__ float selv[TOPK];
    int row = blockIdx.x;
    float* srow = S + (size_t)row * T_NUM;
    for (int j = threadIdx.x; j < T_NUM; j += 256) sv[j] = srow[j];
    __syncthreads();
    for (int it = 0; it < TOPK; it++) {
        float best = -3.f; int bidx = T_NUM;
        for (int j = threadIdx.x; j < T_NUM; j += 256) {
            float v = sv[j];
            if (v > best || (v == best && j < bidx)) { best = v; bidx = j; }
        }
        rv[threadIdx.x] = best; ri[threadIdx.x] = bidx;
        __syncthreads();
        for (int off = 128; off > 0; off >>= 1) {
            if (threadIdx.x < off) {
                float v2 = rv[threadIdx.x + off]; int i2 = ri[threadIdx.x + off];
                if (v2 > rv[threadIdx.x] ||
                    (v2 == rv[threadIdx.x] && i2 < ri[threadIdx.x])) {
                    rv[threadIdx.x] = v2; ri[threadIdx.x] = i2;
                }
            }
            __syncthreads();
        }
        if (threadIdx.x == 0) {
            sel[it] = ri[0]; selv[it] = rv[0];
            sv[ri[0]] = -2.f;   // values are sigmoid in (0,1)
        }
        __syncthreads();
    }
    for (int j = threadIdx.x; j < T_NUM; j += 256) {
        float o = 0.f;
        #pragma unroll
        for (int t = 0; t < TOPK; t++) if (j == sel[t]) o = selv[t];
        srow[j] = o;
    }
    if (threadIdx.x == 0) {
        float s = 0.f;
        #pragma unroll
        for (int t = 0; t < TOPK; t++) s += selv[t];
        if (s == 0.f) s = 1.f;
        nd_out[row] = rsqrtf(s);
    }
}

// ---------------- strided copy (concat assembly) ----------------
__global__ void copy_strided(float* __restrict__ dst, int ldd,
                             const float* __restrict__ src, int lds,
                             int rows, int cols) {
    int c = blockIdx.x * blockDim.x + threadIdx.x;
    int r = blockIdx.y;
    if (c < cols && r < rows)
        dst[(size_t)r * ldd + c] = src[(size_t)r * lds + c];
}

// ---------------- fused SGEMM ----------------
// C = EPI( rowscale[m] * sum_k ( A(m,k)*kscale[k] ) * B(k,n) )
// TA: A stored [K,M] (read transposed).  TB: B stored [N,K] (read transposed).
// EPI: 0 = none, 1 = relu, 2 = sigmoid.
template <bool TA, bool TB, int EPI>
__global__ __launch_bounds__(256)
void gemm_kernel(const float* __restrict__ A, const float* __restrict__ B,
                 float* __restrict__ C,
                 int M, int N, int K, int lda, int ldb, int ldc,
                 const float* __restrict__ rowscale,
                 const float* __restrict__ kscale) {
    const int BM = 64, BN = 64, BK = 16;
    __shared__ float As[BK][BM];
    __shared__ float Bs[BK][BN];

    int bm = blockIdx.y * BM;
    int bn = blockIdx.x * BN;
    int tid = threadIdx.x;
    int tx = tid % 16;      // N direction
    int ty = tid / 16;      // M direction

    float acc[4][4];
    #pragma unroll
    for (int i = 0; i < 4; i++)
        #pragma unroll
        for (int j = 0; j < 4; j++) acc[i][j] = 0.f;

    for (int k0 = 0; k0 < K; k0 += BK) {
        // ---- load A tile into As[k][m] ----
        if (!TA) {
            int m = tid / 4;
            int kbase = (tid % 4) * 4;
            int gm = bm + m;
            #pragma unroll
            for (int u = 0; u < 4; u++) {
                int k = kbase + u, gk = k0 + k;
                float v = 0.f;
                if (gm < M && gk < K) {
                    v = A[(size_t)gm * lda + gk];
                    if (kscale) v *= kscale[gk];
                }
                As[k][m] = v;
            }
        } else {
            int k = tid / 16, gk = k0 + k;
            int mbase = (tid % 16) * 4;
            float ks = 1.f;
            if (kscale && gk < K) ks = kscale[gk];
            #pragma unroll
            for (int u = 0; u < 4; u++) {
                int m = mbase + u, gm = bm + m;
                float v = 0.f;
                if (gm < M && gk < K) v = A[(size_t)gk * lda + gm] * ks;
                As[k][m] = v;
            }
        }
        // ---- load B tile into Bs[k][n] ----
        if (!TB) {
            int k = tid / 16, gk = k0 + k;
            int nbase = (tid % 16) * 4;
            #pragma unroll
            for (int u = 0; u < 4; u++) {
                int n = nbase + u, gn = bn + n;
                float v = 0.f;
                if (gk < K && gn < N) v = B[(size_t)gk * ldb + gn];
                Bs[k][n] = v;
            }
        } else {
            int n = tid / 4, gn = bn + n;
            int kbase = (tid % 4) * 4;
            #pragma unroll
            for (int u = 0; u < 4; u++) {
                int k = kbase + u, gk = k0 + k;
                float v = 0.f;
                if (gn < N && gk < K) v = B[(size_t)gn * ldb + gk];
                Bs[k][n] = v;
            }
        }
        __syncthreads();
        #pragma unroll
        for (int kk = 0; kk < BK; kk++) {
            float a[4], b[4];
            #pragma unroll
            for (int i = 0; i < 4; i++) a[i] = As[kk][ty * 4 + i];
            #pragma unroll
            for (int j = 0; j < 4; j++) b[j] = Bs[kk][tx * 4 + j];
            #pragma unroll
            for (int i = 0; i < 4; i++)
                #pragma unroll
                for (int j = 0; j < 4; j++) acc[i][j] += a[i] * b[j];
        }
        __syncthreads();
    }

    #pragma unroll
    for (int i = 0; i < 4; i++) {
        int gm = bm + ty * 4 + i;
        if (gm >= M) continue;
        float rs = rowscale ? rowscale[gm] : 1.f;
        #pragma unroll
        for (int j = 0; j < 4; j++) {
            int gn = bn + tx * 4 + j;
            if (gn >= N) continue;
            float v = acc[i][j] * rs;
            if (EPI == 1) v = fmaxf(v, 0.f);
            else if (EPI == 2) v = 1.f / (1.f + expf(-v));
            C[(size_t)gm * ldc + gn] = v;
        }
    }
}

// ---------------- host orchestration ----------------
static inline dim3 gemm_grid(int M, int N) {
    return dim3((N + 63) / 64, (M + 63) / 64);
}

extern "C" void kernel_launch(void* const* d_in, const int* in_sizes, int n_in,
                              void* d_out, int out_size) {
    const float* R    = (const float*)d_in[0];
    const float* Dm   = (const float*)d_in[1];
    const float* Tm   = (const float*)d_in[2];
    const float* H_d  = (const float*)d_in[3];
    const float* H_t  = (const float*)d_in[4];
    const float* W1g[2] = {(const float*)d_in[5], (const float*)d_in[7]};
    const float* W2g[2] = {(const float*)d_in[6], (const float*)d_in[8]};
    const float* Wd[2]  = {(const float*)d_in[9], (const float*)d_in[11]};
    const float* Wt[2]  = {(const float*)d_in[10], (const float*)d_in[12]};
    const float* WdO  = (const float*)d_in[13];
    const float* WtO  = (const float*)d_in[14];
    float* out = (float*)d_out;

    float *S, *catd, *catt, *hdb, *htb, *hdp, *htp, *sd, *st, *nd, *nt, *part;
    cudaGetSymbolAddress((void**)&S,    g_S);
    cudaGetSymbolAddress((void**)&catd, g_catd);
    cudaGetSymbolAddress((void**)&catt, g_catt);
    cudaGetSymbolAddress((void**)&hdb,  g_hd);
    cudaGetSymbolAddress((void**)&htb,  g_ht);
    cudaGetSymbolAddress((void**)&hdp,  g_hdp);
    cudaGetSymbolAddress((void**)&htp,  g_htp);
    cudaGetSymbolAddress((void**)&sd,   g_sd);
    cudaGetSymbolAddress((void**)&st,   g_st);
    cudaGetSymbolAddress((void**)&nd,   g_nd);
    cudaGetSymbolAddress((void**)&nt,   g_nt);
    cudaGetSymbolAddress((void**)&part, g_part);

    // symmetric norms of D and T (fixed across levels)
    rowsum_rsqrt<<<D_NUM, 256>>>(Dm, D_NUM, D_NUM, sd);
    rowsum_rsqrt<<<T_NUM, 256>>>(Tm, T_NUM, T_NUM, st);

    const float* hd = H_d;
    const float* ht = H_t;
    int F = FEAT;

    for (int lvl = 0; lvl < 2; lvl++) {
        // --- GL layer: projections + sigmoid relation + top-k prune ---
        gemm_kernel<false, false, 0><<<gemm_grid(D_NUM, UNITS), 256>>>(
            hd, W1g[lvl], hdp, D_NUM, UNITS, F, F, UNITS, UNITS, nullptr, nullptr);
        gemm_kernel<false, false, 0><<<gemm_grid(T_NUM, UNITS), 256>>>(
            ht, W2g[lvl], htp, T_NUM, UNITS, F, F, UNITS, UNITS, nullptr, nullptr);
        gemm_kernel<false, true, 2><<<gemm_grid(D_NUM, T_NUM), 256>>>(
            hdp, htp, S, D_NUM, T_NUM, UNITS, UNITS, UNITS, T_NUM, nullptr, nullptr);
        topk_kernel<<<D_NUM, 256>>>(S, nd);   // in-place prune + row norms
        colsum_partial<<<dim3((T_NUM + 255) / 256, NCHUNK), 256>>>(S, D_NUM, T_NUM, part);
        colsum_finish<<<(T_NUM + 255) / 256, 256>>>(part, T_NUM, nt);

        // --- CGC layer on learned graph ---
        // H_dt = relu(Rn @ ht)    -> catd[:, F:2F]
        gemm_kernel<false, false, 1><<<gemm_grid(D_NUM, F), 256>>>(
            S, ht, catd + F, D_NUM, F, T_NUM, T_NUM, F, 3 * F, nd, nt);
        // H_td = relu(Rn^T @ hd)  -> catt[:, F:2F]
        gemm_kernel<true, false, 1><<<gemm_grid(T_NUM, F), 256>>>(
            S, hd, catt + F, T_NUM, F, D_NUM, T_NUM, F, 3 * F, nt, nd);
        // H_dd = relu(Dn @ hd)    -> catd[:, 2F:3F]
        gemm_kernel<false, false, 1><<<gemm_grid(D_NUM, F), 256>>>(
            Dm, hd, catd + 2 * F, D_NUM, F, D_NUM, D_NUM, F, 3 * F, sd, sd);
        // H_tt = relu(Tn @ ht)    -> catt[:, 2F:3F]
        gemm_kernel<false, false, 1><<<gemm_grid(T_NUM, F), 256>>>(
            Tm, ht, catt + 2 * F, T_NUM, F, T_NUM, T_NUM, F, 3 * F, st, st);
        // identity slices
        copy_strided<<<dim3((F + 255) / 256, D_NUM), 256>>>(catd, 3 * F, hd, F, D_NUM, F);
        copy_strided<<<dim3((F + 255) / 256, T_NUM), 256>>>(catt, 3 * F, ht, F, T_NUM, F);
        // dense + relu
        gemm_kernel<false, false, 1><<<gemm_grid(D_NUM, UNITS), 256>>>(
            catd, Wd[lvl], hdb, D_NUM, UNITS, 3 * F, 3 * F, UNITS, UNITS, nullptr, nullptr);
        gemm_kernel<false, false, 1><<<gemm_grid(T_NUM, UNITS), 256>>>(
            catt, Wt[lvl], htb, T_NUM, UNITS, 3 * F, 3 * F, UNITS, UNITS, nullptr, nullptr);
        hd = hdb; ht = htb; F = UNITS;
    }

    // --- output CGC on original R ---
    rowsum_rsqrt<<<D_NUM, 256>>>(R, D_NUM, T_NUM, nd);
    colsum_partial<<<dim3((T_NUM + 255) / 256, NCHUNK), 256>>>(R, D_NUM, T_NUM, part);
    colsum_finish<<<(T_NUM + 255) / 256, 256>>>(part, T_NUM, nt);

    gemm_kernel<false, false, 1><<<gemm_grid(D_NUM, F), 256>>>(
        R, ht, catd + F, D_NUM, F, T_NUM, T_NUM, F, 3 * F, nd, nt);
    gemm_kernel<true, false, 1><<<gemm_grid(T_NUM, F), 256>>>(
        R, hd, catt + F, T_NUM, F, D_NUM, T_NUM, F, 3 * F, nt, nd);
    gemm_kernel<false, false, 1><<<gemm_grid(D_NUM, F), 256>>>(
        Dm, hd, catd + 2 * F, D_NUM, F, D_NUM, D_NUM, F, 3 * F, sd, sd);
    gemm_kernel<false, false, 1><<<gemm_grid(T_NUM, F), 256>>>(
        Tm, ht, catt + 2 * F, T_NUM, F, T_NUM, T_NUM, F, 3 * F, st, st);
    copy_strided<<<dim3((F + 255) / 256, D_NUM), 256>>>(catd, 3 * F, hd, F, D_NUM, F);
    copy_strided<<<dim3((F + 255) / 256, T_NUM), 256>>>(catt, 3 * F, ht, F, T_NUM, F);

    gemm_kernel<false, false, 1><<<gemm_grid(D_NUM, UNITS), 256>>>(
        catd, WdO, hdp, D_NUM, UNITS, 3 * F, 3 * F, UNITS, UNITS, nullptr, nullptr);
    gemm_kernel<false, false, 1><<<gemm_grid(T_NUM, UNITS), 256>>>(
        catt, WtO, htp, T_NUM, UNITS, 3 * F, 3 * F, UNITS, UNITS, nullptr, nullptr);

    // R_pred = sigmoid(hd_out @ ht_out^T) -> d_out
    gemm_kernel<false, true, 2><<<gemm_grid(D_NUM, T_NUM), 256>>>(
        hdp, htp, out, D_NUM, T_NUM, UNITS, UNITS, UNITS, T_NUM, nullptr, nullptr);
}

// round 2
// speedup vs baseline: 1.0575x; 1.0575x over previous
#include <cuda_runtime.h>
#include <math.h>

#define D_NUM 4000
#define T_NUM 2000
#define FEAT  256
#define UNITS 200
#define TOPK  10
#define NCHUNK 16

// ---------------- scratch (device globals; no runtime allocation) ----------------
__device__ float g_S[(size_t)D_NUM * T_NUM];        // dense sigmoid relation (pre-prune)
__device__ float g_catd[(size_t)D_NUM * 3 * FEAT];  // concat buffer drugs
__device__ float g_catt[(size_t)T_NUM * 3 * FEAT];  // concat buffer targets
__device__ float g_hd[(size_t)D_NUM * FEAT];        // current H_d
__device__ float g_ht[(size_t)T_NUM * FEAT];        // current H_t
__device__ float g_hdp[(size_t)D_NUM * UNITS];      // projected Hd
__device__ float g_htp[(size_t)T_NUM * UNITS];      // projected Ht
__device__ float g_sd[D_NUM];                       // rsqrt(safe(rowsum(D)))
__device__ float g_st[T_NUM];                       // rsqrt(safe(rowsum(T)))
__device__ float g_nd[D_NUM];                       // bipartite row norms
__device__ float g_nt[T_NUM];                       // bipartite col norms
__device__ float g_ntraw[T_NUM];                    // col sums of pruned graph
__device__ float g_part[NCHUNK * T_NUM];            // colsum partials (for R)
__device__ int   g_selidx[D_NUM * TOPK];            // top-k column indices
__device__ float g_selval[D_NUM * TOPK];            // top-k values

// ---------------- reductions ----------------
__global__ void rowsum_rsqrt(const float* __restrict__ A, int rows, int cols,
                             float* __restrict__ out) {
    int row = blockIdx.x;
    if (row >= rows) return;
    const float* a = A + (size_t)row * cols;
    float s = 0.f;
    for (int j = threadIdx.x; j < cols; j += blockDim.x) s += a[j];
    __shared__ float red[256];
    red[threadIdx.x] = s;
    __syncthreads();
    for (int off = 128; off > 0; off >>= 1) {
        if (threadIdx.x < off) red[threadIdx.x] += red[threadIdx.x + off];
        __syncthreads();
    }
    if (threadIdx.x == 0) {
        float n = red[0];
        if (n == 0.f) n = 1.f;
        out[row] = rsqrtf(n);
    }
}

__global__ void colsum_partial(const float* __restrict__ A, int rows, int cols,
                               float* __restrict__ part) {
    int j = blockIdx.x * blockDim.x + threadIdx.x;
    if (j >= cols) return;
    int chunk = (rows + NCHUNK - 1) / NCHUNK;
    int r0 = blockIdx.y * chunk;
    int r1 = r0 + chunk; if (r1 > rows) r1 = rows;
    float s = 0.f;
    for (int i = r0; i < r1; i++) s += A[(size_t)i * cols + j];
    part[blockIdx.y * cols + j] = s;
}

__global__ void colsum_finish(const float* __restrict__ part, int cols,
                              float* __restrict__ out) {
    int j = blockIdx.x * blockDim.x + threadIdx.x;
    if (j >= cols) return;
    float s = 0.f;
    for (int c = 0; c < NCHUNK; c++) s += part[c * cols + j];
    if (s == 0.f) s = 1.f;
    out[j] = rsqrtf(s);
}

// ---------------- small utility kernels ----------------
__global__ void zero_vec(float* __restrict__ p, int n) {
    int i = blockIdx.x * blockDim.x + threadIdx.x;
    if (i < n) p[i] = 0.f;
}

__global__ void zero_strided(float* __restrict__ dst, int ld, int rows, int cols) {
    int c = blockIdx.x * blockDim.x + threadIdx.x;
    int r = blockIdx.y;
    if (c < cols && r < rows) dst[(size_t)r * ld + c] = 0.f;
}

__global__ void relu_strided(float* __restrict__ dst, int ld, int rows, int cols) {
    int c = blockIdx.x * blockDim.x + threadIdx.x;
    int r = blockIdx.y;
    if (c < cols && r < rows) {
        size_t o = (size_t)r * ld + c;
        dst[o] = fmaxf(dst[o], 0.f);
    }
}

__global__ void copy_strided(float* __restrict__ dst, int ldd,
                             const float* __restrict__ src, int lds,
                             int rows, int cols) {
    int c = blockIdx.x * blockDim.x + threadIdx.x;
    int r = blockIdx.y;
    if (c < cols && r < rows)
        dst[(size_t)r * ldd + c] = src[(size_t)r * lds + c];
}

// ---------------- top-k (exact stable-sort tie semantics: min index wins) -------
// Reads dense S, emits (idx,val) pairs per row, row norm nd, and atomic colsums.
__global__ void topk_kernel(const float* __restrict__ S,
                            int* __restrict__ selidx, float* __restrict__ selval,
                            float* __restrict__ nd_out, float* __restrict__ ntraw) {
    __shared__ float sv[T_NUM];
    __shared__ float rv[256];
    __shared__ int   ri[256];
    __shared__ int   sel[TOPK];
    __shared__ float selv[TOPK];
    int row = blockIdx.x;
    const float* srow = S + (size_t)row * T_NUM;
    for (int j = threadIdx.x; j < T_NUM; j += 256) sv[j] = srow[j];
    __syncthreads();
    for (int it = 0; it < TOPK; it++) {
        float best = -3.f; int bidx = T_NUM;
        for (int j = threadIdx.x; j < T_NUM; j += 256) {
            float v = sv[j];
            if (v > best || (v == best && j < bidx)) { best = v; bidx = j; }
        }
        rv[threadIdx.x] = best; ri[threadIdx.x] = bidx;
        __syncthreads();
        for (int off = 128; off > 0; off >>= 1) {
            if (threadIdx.x < off) {
                float v2 = rv[threadIdx.x + off]; int i2 = ri[threadIdx.x + off];
                if (v2 > rv[threadIdx.x] ||
                    (v2 == rv[threadIdx.x] && i2 < ri[threadIdx.x])) {
                    rv[threadIdx.x] = v2; ri[threadIdx.x] = i2;
                }
            }
            __syncthreads();
        }
        if (threadIdx.x == 0) {
            sel[it] = ri[0]; selv[it] = rv[0];
            sv[ri[0]] = -2.f;   // values are sigmoid in (0,1)
        }
        __syncthreads();
    }
    if (threadIdx.x < TOPK) {
        selidx[row * TOPK + threadIdx.x] = sel[threadIdx.x];
        selval[row * TOPK + threadIdx.x] = selv[threadIdx.x];
        atomicAdd(&ntraw[sel[threadIdx.x]], selv[threadIdx.x]);
    }
    if (threadIdx.x == 0) {
        float s = 0.f;
        #pragma unroll
        for (int t = 0; t < TOPK; t++) s += selv[t];
        if (s == 0.f) s = 1.f;
        nd_out[row] = rsqrtf(s);
    }
}

__global__ void nt_finish(const float* __restrict__ raw, float* __restrict__ out, int n) {
    int i = blockIdx.x * blockDim.x + threadIdx.x;
    if (i < n) {
        float s = raw[i];
        if (s == 0.f) s = 1.f;
        out[i] = rsqrtf(s);
    }
}

// ---------------- sparse CGC kernels ----------------
// H_dt[d,:] = relu( nd[d] * sum_j selval[d,j]*nt[c_j] * ht[c_j,:] )
__global__ void gather_dt(const int* __restrict__ selidx, const float* __restrict__ selval,
                          const float* __restrict__ nd, const float* __restrict__ nt,
                          const float* __restrict__ ht, int F,
                          float* __restrict__ outd, int ldo) {
    int d = blockIdx.x;
    __shared__ int   ci[TOPK];
    __shared__ float cw[TOPK];
    if (threadIdx.x < TOPK) {
        int c = selidx[d * TOPK + threadIdx.x];
        ci[threadIdx.x] = c;
        cw[threadIdx.x] = selval[d * TOPK + threadIdx.x] * nt[c];
    }
    __syncthreads();
    float ndv = nd[d];
    for (int f = threadIdx.x; f < F; f += blockDim.x) {
        float s = 0.f;
        #pragma unroll
        for (int j = 0; j < TOPK; j++) s += cw[j] * ht[(size_t)ci[j] * F + f];
        outd[(size_t)d * ldo + f] = fmaxf(s * ndv, 0.f);
    }
}

// H_td accumulation: for each edge (d -> t, w), outt[t,:] += w * hd[d,:]
__global__ void scatter_td(const int* __restrict__ selidx, const float* __restrict__ selval,
                           const float* __restrict__ nd, const float* __restrict__ nt,
                           const float* __restrict__ hd, int F,
                           float* __restrict__ outt, int ldo) {
    int e = blockIdx.x;
    int d = e / TOPK;
    int t = selidx[e];
    float w = selval[e] * nd[d] * nt[t];
    const float* src = hd + (size_t)d * F;
    float* dst = outt + (size_t)t * ldo;
    for (int f = threadIdx.x; f < F; f += blockDim.x)
        atomicAdd(&dst[f], w * src[f]);
}

// ---------------- fused SGEMM: 128x64x16 tiles, 8x4 per thread ----------------
// C = EPI( rowscale[m] * sum_k ( A(m,k)*kscale[k] ) * B(k,n) )
// TA: A stored [K,M] (read transposed).  TB: B stored [N,K] (read transposed).
// EPI: 0 = none, 1 = relu, 2 = sigmoid.
template <bool TA, bool TB, int EPI>
__global__ __launch_bounds__(256)
void gemm_kernel(const float* __restrict__ A, const float* __restrict__ B,
                 float* __restrict__ C,
                 int M, int N, int K, int lda, int ldb, int ldc,
                 const float* __restrict__ rowscale,
                 const float* __restrict__ kscale) {
    const int BM = 128, BN = 64, BK = 16;
    __shared__ float As[BK][BM];
    __shared__ float Bs[BK][BN];

    int bm = blockIdx.y * BM;
    int bn = blockIdx.x * BN;
    int tid = threadIdx.x;
    int tx = tid & 15;      // N direction (x4)
    int ty = tid >> 4;      // M direction (x8)

    float acc[8][4];
    #pragma unroll
    for (int i = 0; i < 8; i++)
        #pragma unroll
        for (int j = 0; j < 4; j++) acc[i][j] = 0.f;

    for (int k0 = 0; k0 < K; k0 += BK) {
        // ---- load A tile into As[k][m] (128x16 = 8 elems/thread) ----
        if (!TA) {
            int m = tid >> 1;
            int kq = (tid & 1) * 8;
            int gm = bm + m;
            #pragma unroll
            for (int u = 0; u < 8; u++) {
                int k = kq + u, gk = k0 + k;
                float v = 0.f;
                if (gm < M && gk < K) {
                    v = A[(size_t)gm * lda + gk];
                    if (kscale) v *= kscale[gk];
                }
                As[k][m] = v;
            }
        } else {
            int k = tid >> 4, gk = k0 + k;
            int mq = (tid & 15) * 8;
            float ks = 1.f;
            if (kscale && gk < K) ks = kscale[gk];
            #pragma unroll
            for (int u = 0; u < 8; u++) {
                int m = mq + u, gm = bm + m;
                float v = 0.f;
                if (gm < M && gk < K) v = A[(size_t)gk * lda + gm] * ks;
                As[k][m] = v;
            }
        }
        // ---- load B tile into Bs[k][n] (64x16 = 4 elems/thread) ----
        if (!TB) {
            int k = tid >> 4, gk = k0 + k;
            int nq = (tid & 15) * 4;
            #pragma unroll
            for (int u = 0; u < 4; u++) {
                int n = nq + u, gn = bn + n;
                float v = 0.f;
                if (gk < K && gn < N) v = B[(size_t)gk * ldb + gn];
                Bs[k][n] = v;
            }
        } else {
            int n = tid >> 2, gn = bn + n;
            int kq = (tid & 3) * 4;
            #pragma unroll
            for (int u = 0; u < 4; u++) {
                int k = kq + u, gk = k0 + k;
                float v = 0.f;
                if (gn < N && gk < K) v = B[(size_t)gn * ldb + gk];
                Bs[k][n] = v;
            }
        }
        __syncthreads();
        #pragma unroll
        for (int kk = 0; kk < BK; kk++) {
            float4 a0 = *reinterpret_cast<const float4*>(&As[kk][ty * 8]);
            float4 a1 = *reinterpret_cast<const float4*>(&As[kk][ty * 8 + 4]);
            float4 b0 = *reinterpret_cast<const float4*>(&Bs[kk][tx * 4]);
            float a[8] = {a0.x, a0.y, a0.z, a0.w, a1.x, a1.y, a1.z, a1.w};
            float b[4] = {b0.x, b0.y, b0.z, b0.w};
            #pragma unroll
            for (int i = 0; i < 8; i++)
                #pragma unroll
                for (int j = 0; j < 4; j++) acc[i][j] += a[i] * b[j];
        }
        __syncthreads();
    }

    #pragma unroll
    for (int i = 0; i < 8; i++) {
        int gm = bm + ty * 8 + i;
        if (gm >= M) continue;
        float rs = rowscale ? rowscale[gm] : 1.f;
        #pragma unroll
        for (int j = 0; j < 4; j++) {
            int gn = bn + tx * 4 + j;
            if (gn >= N) continue;
            float v = acc[i][j] * rs;
            if (EPI == 1) v = fmaxf(v, 0.f);
            else if (EPI == 2) v = 1.f / (1.f + expf(-v));
            C[(size_t)gm * ldc + gn] = v;
        }
    }
}

static inline dim3 gemm_grid(int M, int N) {
    return dim3((N + 63) / 64, (M + 127) / 128);
}

// ---------------- host orchestration ----------------
extern "C" void kernel_launch(void* const* d_in, const int* in_sizes, int n_in,
                              void* d_out, int out_size) {
    const float* R    = (const float*)d_in[0];
    const float* Dm   = (const float*)d_in[1];
    const float* Tm   = (const float*)d_in[2];
    const float* H_d  = (const float*)d_in[3];
    const float* H_t  = (const float*)d_in[4];
    const float* W1g[2] = {(const float*)d_in[5], (const float*)d_in[7]};
    const float* W2g[2] = {(const float*)d_in[6], (const float*)d_in[8]};
    const float* Wd[2]  = {(const float*)d_in[9], (const float*)d_in[11]};
    const float* Wt[2]  = {(const float*)d_in[10], (const float*)d_in[12]};
    const float* WdO  = (const float*)d_in[13];
    const float* WtO  = (const float*)d_in[14];
    float* out = (float*)d_out;

    float *S, *catd, *catt, *hdb, *htb, *hdp, *htp, *sd, *st, *nd, *nt, *ntraw, *part, *selval;
    int* selidx;
    cudaGetSymbolAddress((void**)&S,     g_S);
    cudaGetSymbolAddress((void**)&catd,  g_catd);
    cudaGetSymbolAddress((void**)&catt,  g_catt);
    cudaGetSymbolAddress((void**)&hdb,   g_hd);
    cudaGetSymbolAddress((void**)&htb,   g_ht);
    cudaGetSymbolAddress((void**)&hdp,   g_hdp);
    cudaGetSymbolAddress((void**)&htp,   g_htp);
    cudaGetSymbolAddress((void**)&sd,    g_sd);
    cudaGetSymbolAddress((void**)&st,    g_st);
    cudaGetSymbolAddress((void**)&nd,    g_nd);
    cudaGetSymbolAddress((void**)&nt,    g_nt);
    cudaGetSymbolAddress((void**)&ntraw, g_ntraw);
    cudaGetSymbolAddress((void**)&part,  g_part);
    cudaGetSymbolAddress((void**)&selidx, g_selidx);
    cudaGetSymbolAddress((void**)&selval, g_selval);

    // symmetric norms of D and T (fixed across levels)
    rowsum_rsqrt<<<D_NUM, 256>>>(Dm, D_NUM, D_NUM, sd);
    rowsum_rsqrt<<<T_NUM, 256>>>(Tm, T_NUM, T_NUM, st);

    const float* hd = H_d;
    const float* ht = H_t;
    int F = FEAT;

    for (int lvl = 0; lvl < 2; lvl++) {
        // --- GL layer: projections + sigmoid relation + top-k prune ---
        gemm_kernel<false, false, 0><<<gemm_grid(D_NUM, UNITS), 256>>>(
            hd, W1g[lvl], hdp, D_NUM, UNITS, F, F, UNITS, UNITS, nullptr, nullptr);
        gemm_kernel<false, false, 0><<<gemm_grid(T_NUM, UNITS), 256>>>(
            ht, W2g[lvl], htp, T_NUM, UNITS, F, F, UNITS, UNITS, nullptr, nullptr);
        gemm_kernel<false, true, 2><<<gemm_grid(D_NUM, T_NUM), 256>>>(
            hdp, htp, S, D_NUM, T_NUM, UNITS, UNITS, UNITS, T_NUM, nullptr, nullptr);

        zero_vec<<<(T_NUM + 255) / 256, 256>>>(ntraw, T_NUM);
        topk_kernel<<<D_NUM, 256>>>(S, selidx, selval, nd, ntraw);
        nt_finish<<<(T_NUM + 255) / 256, 256>>>(ntraw, nt, T_NUM);

        // --- CGC layer on learned (sparse: 10 nnz/row) graph ---
        // H_dt = relu(Rn @ ht) -> catd[:, F:2F]   (gather)
        gather_dt<<<D_NUM, 256>>>(selidx, selval, nd, nt, ht, F, catd + F, 3 * F);
        // H_td = relu(Rn^T @ hd) -> catt[:, F:2F] (zero + scatter + relu)
        zero_strided<<<dim3((F + 255) / 256, T_NUM), 256>>>(catt + F, 3 * F, T_NUM, F);
        scatter_td<<<D_NUM * TOPK, 256>>>(selidx, selval, nd, nt, hd, F, catt + F, 3 * F);
        relu_strided<<<dim3((F + 255) / 256, T_NUM), 256>>>(catt + F, 3 * F, T_NUM, F);
        // H_dd = relu(Dn @ hd) -> catd[:, 2F:3F]
        gemm_kernel<false, false, 1><<<gemm_grid(D_NUM, F), 256>>>(
            Dm, hd, catd + 2 * F, D_NUM, F, D_NUM, D_NUM, F, 3 * F, sd, sd);
        // H_tt = relu(Tn @ ht) -> catt[:, 2F:3F]
        gemm_kernel<false, false, 1><<<gemm_grid(T_NUM, F), 256>>>(
            Tm, ht, catt + 2 * F, T_NUM, F, T_NUM, T_NUM, F, 3 * F, st, st);
        // identity slices
        copy_strided<<<dim3((F + 255) / 256, D_NUM), 256>>>(catd, 3 * F, hd, F, D_NUM, F);
        copy_strided<<<dim3((F + 255) / 256, T_NUM), 256>>>(catt, 3 * F, ht, F, T_NUM, F);
        // dense + relu
        gemm_kernel<false, false, 1><<<gemm_grid(D_NUM, UNITS), 256>>>(
            catd, Wd[lvl], hdb, D_NUM, UNITS, 3 * F, 3 * F, UNITS, UNITS, nullptr, nullptr);
        gemm_kernel<false, false, 1><<<gemm_grid(T_NUM, UNITS), 256>>>(
            catt, Wt[lvl], htb, T_NUM, UNITS, 3 * F, 3 * F, UNITS, UNITS, nullptr, nullptr);
        hd = hdb; ht = htb; F = UNITS;
    }

    // --- output CGC on original (dense) R ---
    rowsum_rsqrt<<<D_NUM, 256>>>(R, D_NUM, T_NUM, nd);
    colsum_partial<<<dim3((T_NUM + 255) / 256, NCHUNK), 256>>>(R, D_NUM, T_NUM, part);
    colsum_finish<<<(T_NUM + 255) / 256, 256>>>(part, T_NUM, nt);

    gemm_kernel<false, false, 1><<<gemm_grid(D_NUM, F), 256>>>(
        R, ht, catd + F, D_NUM, F, T_NUM, T_NUM, F, 3 * F, nd, nt);
    gemm_kernel<true, false, 1><<<gemm_grid(T_NUM, F), 256>>>(
        R, hd, catt + F, T_NUM, F, D_NUM, T_NUM, F, 3 * F, nt, nd);
    gemm_kernel<false, false, 1><<<gemm_grid(D_NUM, F), 256>>>(
        Dm, hd, catd + 2 * F, D_NUM, F, D_NUM, D_NUM, F, 3 * F, sd, sd);
    gemm_kernel<false, false, 1><<<gemm_grid(T_NUM, F), 256>>>(
        Tm, ht, catt + 2 * F, T_NUM, F, T_NUM, T_NUM, F, 3 * F, st, st);
    copy_strided<<<dim3((F + 255) / 256, D_NUM), 256>>>(catd, 3 * F, hd, F, D_NUM, F);
    copy_strided<<<dim3((F + 255) / 256, T_NUM), 256>>>(catt, 3 * F, ht, F, T_NUM, F);

    gemm_kernel<false, false, 1><<<gemm_grid(D_NUM, UNITS), 256>>>(
        catd, WdO, hdp, D_NUM, UNITS, 3 * F, 3 * F, UNITS, UNITS, nullptr, nullptr);
    gemm_kernel<false, false, 1><<<gemm_grid(T_NUM, UNITS), 256>>>(
        catt, WtO, htp, T_NUM, UNITS, 3 * F, 3 * F, UNITS, UNITS, nullptr, nullptr);

    // R_pred = sigmoid(hd_out @ ht_out^T) -> d_out
    gemm_kernel<false, true, 2><<<gemm_grid(D_NUM, T_NUM), 256>>>(
        hdp, htp, out, D_NUM, T_NUM, UNITS, UNITS, UNITS, T_NUM, nullptr, nullptr);
}

// round 3
// speedup vs baseline: 1.9893x; 1.8812x over previous
#include <cuda_runtime.h>
#include <math.h>
#include <stdint.h>

#define D_NUM 4000
#define T_NUM 2000
#define FEAT  256
#define UNITS 200
#define TOPK  10
#define NCHUNK 16

// ---------------- scratch (device globals; no runtime allocation) ----------------
__device__ float g_S[(size_t)D_NUM * T_NUM];        // dense sigmoid relation (pre-prune)
__device__ float g_catd[(size_t)D_NUM * 3 * FEAT];  // concat buffer drugs
__device__ float g_catt[(size_t)T_NUM * 3 * FEAT];  // concat buffer targets
__device__ float g_hd[(size_t)D_NUM * FEAT];        // current H_d
__device__ float g_ht[(size_t)T_NUM * FEAT];        // current H_t
__device__ float g_hdp[(size_t)D_NUM * UNITS];      // projected Hd
__device__ float g_htp[(size_t)T_NUM * UNITS];      // projected Ht
__device__ float g_sd[D_NUM];                       // rsqrt(safe(rowsum(D)))
__device__ float g_st[T_NUM];                       // rsqrt(safe(rowsum(T)))
__device__ float g_nd[D_NUM];                       // bipartite row norms
__device__ float g_nt[T_NUM];                       // bipartite col norms
__device__ float g_ntraw[T_NUM];                    // col sums of pruned graph
__device__ float g_part[NCHUNK * T_NUM];            // colsum partials (for R)
__device__ int   g_selidx[D_NUM * TOPK];            // top-k column indices
__device__ float g_selval[D_NUM * TOPK];            // top-k values

// ---------------- reductions ----------------
__global__ void rowsum_rsqrt(const float* __restrict__ A, int rows, int cols,
                             float* __restrict__ out) {
    int row = blockIdx.x;
    if (row >= rows) return;
    const float* a = A + (size_t)row * cols;
    float s = 0.f;
    for (int j = threadIdx.x; j < cols; j += blockDim.x) s += a[j];
    __shared__ float red[256];
    red[threadIdx.x] = s;
    __syncthreads();
    for (int off = 128; off > 0; off >>= 1) {
        if (threadIdx.x < off) red[threadIdx.x] += red[threadIdx.x + off];
        __syncthreads();
    }
    if (threadIdx.x == 0) {
        float n = red[0];
        if (n == 0.f) n = 1.f;
        out[row] = rsqrtf(n);
    }
}

__global__ void colsum_partial(const float* __restrict__ A, int rows, int cols,
                               float* __restrict__ part) {
    int j = blockIdx.x * blockDim.x + threadIdx.x;
    if (j >= cols) return;
    int chunk = (rows + NCHUNK - 1) / NCHUNK;
    int r0 = blockIdx.y * chunk;
    int r1 = r0 + chunk; if (r1 > rows) r1 = rows;
    float s = 0.f;
    for (int i = r0; i < r1; i++) s += A[(size_t)i * cols + j];
    part[blockIdx.y * cols + j] = s;
}

__global__ void colsum_finish(const float* __restrict__ part, int cols,
                              float* __restrict__ out) {
    int j = blockIdx.x * blockDim.x + threadIdx.x;
    if (j >= cols) return;
    float s = 0.f;
    for (int c = 0; c < NCHUNK; c++) s += part[c * cols + j];
    if (s == 0.f) s = 1.f;
    out[j] = rsqrtf(s);
}

// ---------------- small utility kernels ----------------
__global__ void zero_vec(float* __restrict__ p, int n) {
    int i = blockIdx.x * blockDim.x + threadIdx.x;
    if (i < n) p[i] = 0.f;
}

__global__ void zero_strided(float* __restrict__ dst, int ld, int rows, int cols) {
    int c = blockIdx.x * blockDim.x + threadIdx.x;
    int r = blockIdx.y;
    if (c < cols && r < rows) dst[(size_t)r * ld + c] = 0.f;
}

__global__ void relu_strided(float* __restrict__ dst, int ld, int rows, int cols) {
    int c = blockIdx.x * blockDim.x + threadIdx.x;
    int r = blockIdx.y;
    if (c < cols && r < rows) {
        size_t o = (size_t)r * ld + c;
        dst[o] = fmaxf(dst[o], 0.f);
    }
}

__global__ void copy_strided(float* __restrict__ dst, int ldd,
                             const float* __restrict__ src, int lds,
                             int rows, int cols) {
    int c = blockIdx.x * blockDim.x + threadIdx.x;
    int r = blockIdx.y;
    if (c < cols && r < rows)
        dst[(size_t)r * ldd + c] = src[(size_t)r * lds + c];
}

// ---------------- top-k (exact stable-sort tie semantics: min index wins) -------
__global__ void topk_kernel(const float* __restrict__ S,
                            int* __restrict__ selidx, float* __restrict__ selval,
                            float* __restrict__ nd_out, float* __restrict__ ntraw) {
    __shared__ float sv[T_NUM];
    __shared__ float rv[256];
    __shared__ int   ri[256];
    __shared__ int   sel[TOPK];
    __shared__ float selv[TOPK];
    int row = blockIdx.x;
    const float* srow = S + (size_t)row * T_NUM;
    for (int j = threadIdx.x; j < T_NUM; j += 256) sv[j] = srow[j];
    __syncthreads();
    for (int it = 0; it < TOPK; it++) {
        float best = -3.f; int bidx = T_NUM;
        for (int j = threadIdx.x; j < T_NUM; j += 256) {
            float v = sv[j];
            if (v > best || (v == best && j < bidx)) { best = v; bidx = j; }
        }
        rv[threadIdx.x] = best; ri[threadIdx.x] = bidx;
        __syncthreads();
        for (int off = 128; off > 0; off >>= 1) {
            if (threadIdx.x < off) {
                float v2 = rv[threadIdx.x + off]; int i2 = ri[threadIdx.x + off];
                if (v2 > rv[threadIdx.x] ||
                    (v2 == rv[threadIdx.x] && i2 < ri[threadIdx.x])) {
                    rv[threadIdx.x] = v2; ri[threadIdx.x] = i2;
                }
            }
            __syncthreads();
        }
        if (threadIdx.x == 0) {
            sel[it] = ri[0]; selv[it] = rv[0];
            sv[ri[0]] = -2.f;
        }
        __syncthreads();
    }
    if (threadIdx.x < TOPK) {
        selidx[row * TOPK + threadIdx.x] = sel[threadIdx.x];
        selval[row * TOPK + threadIdx.x] = selv[threadIdx.x];
        atomicAdd(&ntraw[sel[threadIdx.x]], selv[threadIdx.x]);
    }
    if (threadIdx.x == 0) {
        float s = 0.f;
        #pragma unroll
        for (int t = 0; t < TOPK; t++) s += selv[t];
        if (s == 0.f) s = 1.f;
        nd_out[row] = rsqrtf(s);
    }
}

__global__ void nt_finish(const float* __restrict__ raw, float* __restrict__ out, int n) {
    int i = blockIdx.x * blockDim.x + threadIdx.x;
    if (i < n) {
        float s = raw[i];
        if (s == 0.f) s = 1.f;
        out[i] = rsqrtf(s);
    }
}

// ---------------- sparse CGC kernels ----------------
__global__ void gather_dt(const int* __restrict__ selidx, const float* __restrict__ selval,
                          const float* __restrict__ nd, const float* __restrict__ nt,
                          const float* __restrict__ ht, int F,
                          float* __restrict__ outd, int ldo) {
    int d = blockIdx.x;
    __shared__ int   ci[TOPK];
    __shared__ float cw[TOPK];
    if (threadIdx.x < TOPK) {
        int c = selidx[d * TOPK + threadIdx.x];
        ci[threadIdx.x] = c;
        cw[threadIdx.x] = selval[d * TOPK + threadIdx.x] * nt[c];
    }
    __syncthreads();
    float ndv = nd[d];
    for (int f = threadIdx.x; f < F; f += blockDim.x) {
        float s = 0.f;
        #pragma unroll
        for (int j = 0; j < TOPK; j++) s += cw[j] * ht[(size_t)ci[j] * F + f];
        outd[(size_t)d * ldo + f] = fmaxf(s * ndv, 0.f);
    }
}

__global__ void scatter_td(const int* __restrict__ selidx, const float* __restrict__ selval,
                           const float* __restrict__ nd, const float* __restrict__ nt,
                           const float* __restrict__ hd, int F,
                           float* __restrict__ outt, int ldo) {
    int e = blockIdx.x;
    int d = e / TOPK;
    int t = selidx[e];
    float w = selval[e] * nd[d] * nt[t];
    const float* src = hd + (size_t)d * F;
    float* dst = outt + (size_t)t * ldo;
    for (int f = threadIdx.x; f < F; f += blockDim.x)
        atomicAdd(&dst[f], w * src[f]);
}

// ---------------- TF32 tensor-core GEMM ----------------
// C = EPI( rowscale[m] * sum_k ( A(m,k)*kscale[k] ) * B(k,n) )
// TA: A stored [K,M].  TB: B stored [N,K].  EPI: 0 none, 1 relu, 2 sigmoid.
// Block tile 128x64x32, 8 warps (4M x 2N), warp tile 32x32 via m16n8k8 tf32 mma.

__device__ __forceinline__ uint32_t f2tf(float x) {
    uint32_t r;
    asm("cvt.rna.tf32.f32 %0, %1;" : "=r"(r) : "f"(x));
    return r;
}

__device__ __forceinline__ void mma_tf32(float c[4], uint32_t a0, uint32_t a1,
                                         uint32_t a2, uint32_t a3,
                                         uint32_t b0, uint32_t b1) {
    asm volatile(
        "mma.sync.aligned.m16n8k8.row.col.f32.tf32.tf32.f32 "
        "{%0,%1,%2,%3}, {%4,%5,%6,%7}, {%8,%9}, {%0,%1,%2,%3};"
        : "+f"(c[0]), "+f"(c[1]), "+f"(c[2]), "+f"(c[3])
        : "r"(a0), "r"(a1), "r"(a2), "r"(a3), "r"(b0), "r"(b1));
}

#define GBM 128
#define GBN 64
#define GBK 32

template <bool TA, bool TB, int EPI>
__global__ __launch_bounds__(256)
void mma_gemm(const float* __restrict__ A, const float* __restrict__ B,
              float* __restrict__ C,
              int M, int N, int K, int lda, int ldb, int ldc,
              const float* __restrict__ rowscale,
              const float* __restrict__ kscale) {
    __shared__ uint32_t As[GBM][GBK + 4];   // [m][k], stride 36 -> conflict-free frags
    __shared__ uint32_t Bs[GBK][GBN + 8];   // [k][n], stride 72 -> conflict-free frags

    int tid = threadIdx.x;
    int lane = tid & 31;
    int warp = tid >> 5;
    int gid = lane >> 2, tig = lane & 3;
    int mw = (warp & 3) * 32;
    int nw = (warp >> 2) * 32;
    int bm = blockIdx.y * GBM;
    int bn = blockIdx.x * GBN;

    float acc[2][4][4];
    #pragma unroll
    for (int i = 0; i < 2; i++)
        #pragma unroll
        for (int j = 0; j < 4; j++)
            #pragma unroll
            for (int l = 0; l < 4; l++) acc[i][j][l] = 0.f;

    for (int k0 = 0; k0 < K; k0 += GBK) {
        // ---- A tile -> As[m][k] (tf32-converted, kscale fused) ----
        if (!TA) {
            int r = tid >> 1;
            int gm = bm + r;
            int kb = (tid & 1) * 16;
            #pragma unroll
            for (int u = 0; u < 4; u++) {
                int k = kb + u * 4, gk = k0 + k;
                float4 v = make_float4(0.f, 0.f, 0.f, 0.f);
                if (gm < M && gk + 4 <= K) {
                    v = *reinterpret_cast<const float4*>(&A[(size_t)gm * lda + gk]);
                    if (kscale) {
                        v.x *= kscale[gk];     v.y *= kscale[gk + 1];
                        v.z *= kscale[gk + 2]; v.w *= kscale[gk + 3];
                    }
                }
                uint4 t4;
                t4.x = f2tf(v.x); t4.y = f2tf(v.y); t4.z = f2tf(v.z); t4.w = f2tf(v.w);
                *reinterpret_cast<uint4*>(&As[r][k]) = t4;
            }
        } else {
            int k = tid >> 3, gk = k0 + k;
            float ks = 1.f;
            if (kscale && gk < K) ks = kscale[gk];
            #pragma unroll
            for (int u = 0; u < 4; u++) {
                int m = (tid & 7) * 16 + u * 4;
                int gm = bm + m;
                float4 v = make_float4(0.f, 0.f, 0.f, 0.f);
                if (gk < K && gm + 4 <= M)
                    v = *reinterpret_cast<const float4*>(&A[(size_t)gk * lda + gm]);
                As[m][k]     = f2tf(v.x * ks);
                As[m + 1][k] = f2tf(v.y * ks);
                As[m + 2][k] = f2tf(v.z * ks);
                As[m + 3][k] = f2tf(v.w * ks);
            }
        }
        // ---- B tile -> Bs[k][n] ----
        if (!TB) {
            int k = tid >> 3, gk = k0 + k;
            #pragma unroll
            for (int u = 0; u < 2; u++) {
                int n = (tid & 7) * 8 + u * 4;
                int gn = bn + n;
                float4 v = make_float4(0.f, 0.f, 0.f, 0.f);
                if (gk < K && gn + 4 <= N)
                    v = *reinterpret_cast<const float4*>(&B[(size_t)gk * ldb + gn]);
                uint4 t4;
                t4.x = f2tf(v.x); t4.y = f2tf(v.y); t4.z = f2tf(v.z); t4.w = f2tf(v.w);
                *reinterpret_cast<uint4*>(&Bs[k][n]) = t4;
            }
        } else {
            int n = tid >> 2;
            int gn = bn + n;
            #pragma unroll
            for (int u = 0; u < 2; u++) {
                int k = (tid & 3) * 8 + u * 4, gk = k0 + k;
                float4 v = make_float4(0.f, 0.f, 0.f, 0.f);
                if (gn < N && gk + 4 <= K)
                    v = *reinterpret_cast<const float4*>(&B[(size_t)gn * ldb + gk]);
                Bs[k][n]     = f2tf(v.x);
                Bs[k + 1][n] = f2tf(v.y);
                Bs[k + 2][n] = f2tf(v.z);
                Bs[k + 3][n] = f2tf(v.w);
            }
        }
        __syncthreads();

        #pragma unroll
        for (int kk = 0; kk < GBK; kk += 8) {
            uint32_t b0[4], b1[4];
            #pragma unroll
            for (int nt = 0; nt < 4; nt++) {
                b0[nt] = Bs[kk + tig][nw + nt * 8 + gid];
                b1[nt] = Bs[kk + tig + 4][nw + nt * 8 + gid];
            }
            #pragma unroll
            for (int mt = 0; mt < 2; mt++) {
                int mb = mw + mt * 16;
                uint32_t a0 = As[mb + gid][kk + tig];
                uint32_t a1 = As[mb + gid + 8][kk + tig];
                uint32_t a2 = As[mb + gid][kk + tig + 4];
                uint32_t a3 = As[mb + gid + 8][kk + tig + 4];
                #pragma unroll
                for (int nt = 0; nt < 4; nt++)
                    mma_tf32(acc[mt][nt], a0, a1, a2, a3, b0[nt], b1[nt]);
            }
        }
        __syncthreads();
    }

    // ---- epilogue ----
    #pragma unroll
    for (int mt = 0; mt < 2; mt++) {
        int gm0 = bm + mw + mt * 16 + gid;
        int gm1 = gm0 + 8;
        float rs0 = 1.f, rs1 = 1.f;
        if (rowscale) {
            if (gm0 < M) rs0 = rowscale[gm0];
            if (gm1 < M) rs1 = rowscale[gm1];
        }
        #pragma unroll
        for (int nt = 0; nt < 4; nt++) {
            int gn0 = bn + nw + nt * 8 + 2 * tig;
            int gn1 = gn0 + 1;
            float v;
            if (gm0 < M) {
                if (gn0 < N) {
                    v = acc[mt][nt][0] * rs0;
                    if (EPI == 1) v = fmaxf(v, 0.f);
                    else if (EPI == 2) v = 1.f / (1.f + expf(-v));
                    C[(size_t)gm0 * ldc + gn0] = v;
                }
                if (gn1 < N) {
                    v = acc[mt][nt][1] * rs0;
                    if (EPI == 1) v = fmaxf(v, 0.f);
                    else if (EPI == 2) v = 1.f / (1.f + expf(-v));
                    C[(size_t)gm0 * ldc + gn1] = v;
                }
            }
            if (gm1 < M) {
                if (gn0 < N) {
                    v = acc[mt][nt][2] * rs1;
                    if (EPI == 1) v = fmaxf(v, 0.f);
                    else if (EPI == 2) v = 1.f / (1.f + expf(-v));
                    C[(size_t)gm1 * ldc + gn0] = v;
                }
                if (gn1 < N) {
                    v = acc[mt][nt][3] * rs1;
                    if (EPI == 1) v = fmaxf(v, 0.f);
                    else if (EPI == 2) v = 1.f / (1.f + expf(-v));
                    C[(size_t)gm1 * ldc + gn1] = v;
                }
            }
        }
    }
}

static inline dim3 gemm_grid(int M, int N) {
    return dim3((N + GBN - 1) / GBN, (M + GBM - 1) / GBM);
}

// ---------------- host orchestration ----------------
extern "C" void kernel_launch(void* const* d_in, const int* in_sizes, int n_in,
                              void* d_out, int out_size) {
    const float* R    = (const float*)d_in[0];
    const float* Dm   = (const float*)d_in[1];
    const float* Tm   = (const float*)d_in[2];
    const float* H_d  = (const float*)d_in[3];
    const float* H_t  = (const float*)d_in[4];
    const float* W1g[2] = {(const float*)d_in[5], (const float*)d_in[7]};
    const float* W2g[2] = {(const float*)d_in[6], (const float*)d_in[8]};
    const float* Wd[2]  = {(const float*)d_in[9], (const float*)d_in[11]};
    const float* Wt[2]  = {(const float*)d_in[10], (const float*)d_in[12]};
    const float* WdO  = (const float*)d_in[13];
    const float* WtO  = (const float*)d_in[14];
    float* out = (float*)d_out;

    float *S, *catd, *catt, *hdb, *htb, *hdp, *htp, *sd, *st, *nd, *nt, *ntraw, *part, *selval;
    int* selidx;
    cudaGetSymbolAddress((void**)&S,     g_S);
    cudaGetSymbolAddress((void**)&catd,  g_catd);
    cudaGetSymbolAddress((void**)&catt,  g_catt);
    cudaGetSymbolAddress((void**)&hdb,   g_hd);
    cudaGetSymbolAddress((void**)&htb,   g_ht);
    cudaGetSymbolAddress((void**)&hdp,   g_hdp);
    cudaGetSymbolAddress((void**)&htp,   g_htp);
    cudaGetSymbolAddress((void**)&sd,    g_sd);
    cudaGetSymbolAddress((void**)&st,    g_st);
    cudaGetSymbolAddress((void**)&nd,    g_nd);
    cudaGetSymbolAddress((void**)&nt,    g_nt);
    cudaGetSymbolAddress((void**)&ntraw, g_ntraw);
    cudaGetSymbolAddress((void**)&part,  g_part);
    cudaGetSymbolAddress((void**)&selidx, g_selidx);
    cudaGetSymbolAddress((void**)&selval, g_selval);

    rowsum_rsqrt<<<D_NUM, 256>>>(Dm, D_NUM, D_NUM, sd);
    rowsum_rsqrt<<<T_NUM, 256>>>(Tm, T_NUM, T_NUM, st);

    const float* hd = H_d;
    const float* ht = H_t;
    int F = FEAT;

    for (int lvl = 0; lvl < 2; lvl++) {
        // --- GL layer ---
        mma_gemm<false, false, 0><<<gemm_grid(D_NUM, UNITS), 256>>>(
            hd, W1g[lvl], hdp, D_NUM, UNITS, F, F, UNITS, UNITS, nullptr, nullptr);
        mma_gemm<false, false, 0><<<gemm_grid(T_NUM, UNITS), 256>>>(
            ht, W2g[lvl], htp, T_NUM, UNITS, F, F, UNITS, UNITS, nullptr, nullptr);
        mma_gemm<false, true, 2><<<gemm_grid(D_NUM, T_NUM), 256>>>(
            hdp, htp, S, D_NUM, T_NUM, UNITS, UNITS, UNITS, T_NUM, nullptr, nullptr);

        zero_vec<<<(T_NUM + 255) / 256, 256>>>(ntraw, T_NUM);
        topk_kernel<<<D_NUM, 256>>>(S, selidx, selval, nd, ntraw);
        nt_finish<<<(T_NUM + 255) / 256, 256>>>(ntraw, nt, T_NUM);

        // --- CGC layer on sparse learned graph ---
        gather_dt<<<D_NUM, 256>>>(selidx, selval, nd, nt, ht, F, catd + F, 3 * F);
        zero_strided<<<dim3((F + 255) / 256, T_NUM), 256>>>(catt + F, 3 * F, T_NUM, F);
        scatter_td<<<D_NUM * TOPK, 256>>>(selidx, selval, nd, nt, hd, F, catt + F, 3 * F);
        relu_strided<<<dim3((F + 255) / 256, T_NUM), 256>>>(catt + F, 3 * F, T_NUM, F);
        mma_gemm<false, false, 1><<<gemm_grid(D_NUM, F), 256>>>(
            Dm, hd, catd + 2 * F, D_NUM, F, D_NUM, D_NUM, F, 3 * F, sd, sd);
        mma_gemm<false, false, 1><<<gemm_grid(T_NUM, F), 256>>>(
            Tm, ht, catt + 2 * F, T_NUM, F, T_NUM, T_NUM, F, 3 * F, st, st);
        copy_strided<<<dim3((F + 255) / 256, D_NUM), 256>>>(catd, 3 * F, hd, F, D_NUM, F);
        copy_strided<<<dim3((F + 255) / 256, T_NUM), 256>>>(catt, 3 * F, ht, F, T_NUM, F);
        mma_gemm<false, false, 1><<<gemm_grid(D_NUM, UNITS), 256>>>(
            catd, Wd[lvl], hdb, D_NUM, UNITS, 3 * F, 3 * F, UNITS, UNITS, nullptr, nullptr);
        mma_gemm<false, false, 1><<<gemm_grid(T_NUM, UNITS), 256>>>(
            catt, Wt[lvl], htb, T_NUM, UNITS, 3 * F, 3 * F, UNITS, UNITS, nullptr, nullptr);
        hd = hdb; ht = htb; F = UNITS;
    }

    // --- output CGC on original (dense) R ---
    rowsum_rsqrt<<<D_NUM, 256>>>(R, D_NUM, T_NUM, nd);
    colsum_partial<<<dim3((T_NUM + 255) / 256, NCHUNK), 256>>>(R, D_NUM, T_NUM, part);
    colsum_finish<<<(T_NUM + 255) / 256, 256>>>(part, T_NUM, nt);

    mma_gemm<false, false, 1><<<gemm_grid(D_NUM, F), 256>>>(
        R, ht, catd + F, D_NUM, F, T_NUM, T_NUM, F, 3 * F, nd, nt);
    mma_gemm<true, false, 1><<<gemm_grid(T_NUM, F), 256>>>(
        R, hd, catt + F, T_NUM, F, D_NUM, T_NUM, F, 3 * F, nt, nd);
    mma_gemm<false, false, 1><<<gemm_grid(D_NUM, F), 256>>>(
        Dm, hd, catd + 2 * F, D_NUM, F, D_NUM, D_NUM, F, 3 * F, sd, sd);
    mma_gemm<false, false, 1><<<gemm_grid(T_NUM, F), 256>>>(
        Tm, ht, catt + 2 * F, T_NUM, F, T_NUM, T_NUM, F, 3 * F, st, st);
    copy_strided<<<dim3((F + 255) / 256, D_NUM), 256>>>(catd, 3 * F, hd, F, D_NUM, F);
    copy_strided<<<dim3((F + 255) / 256, T_NUM), 256>>>(catt, 3 * F, ht, F, T_NUM, F);

    mma_gemm<false, false, 1><<<gemm_grid(D_NUM, UNITS), 256>>>(
        catd, WdO, hdp, D_NUM, UNITS, 3 * F, 3 * F, UNITS, UNITS, nullptr, nullptr);
    mma_gemm<false, false, 1><<<gemm_grid(T_NUM, UNITS), 256>>>(
        catt, WtO, htp, T_NUM, UNITS, 3 * F, 3 * F, UNITS, UNITS, nullptr, nullptr);

    mma_gemm<false, true, 2><<<gemm_grid(D_NUM, T_NUM), 256>>>(
        hdp, htp, out, D_NUM, T_NUM, UNITS, UNITS, UNITS, T_NUM, nullptr, nullptr);
}